// round 15
// baseline (speedup 1.0000x reference)
#include <cuda_runtime.h>
#include <cuda_bf16.h>
#include <math.h>
#include <stdint.h>

#define Bb   32
#define Ss   577
#define Hh   1024
#define NH_  16
#define DH_  64
#define NTOK (Bb*Ss)          // 18464

// ---------------- scratch (__device__ globals; no allocs allowed) ----------
__device__ __align__(16) __nv_bfloat16 g_Xh[(size_t)NTOK*Hh];
__device__ __align__(16) __nv_bfloat16 g_Xl[(size_t)NTOK*Hh];
__device__ __align__(16) __nv_bfloat16 g_Wh[(size_t)4*Hh*Hh];
__device__ __align__(16) __nv_bfloat16 g_Wl[(size_t)4*Hh*Hh];
// head-major [B,NH,S,DH] bf16 hi/lo
__device__ __align__(16) __nv_bfloat16 g_Qh[(size_t)NTOK*Hh];
__device__ __align__(16) __nv_bfloat16 g_Ql[(size_t)NTOK*Hh];
__device__ __align__(16) __nv_bfloat16 g_Kh[(size_t)NTOK*Hh];
__device__ __align__(16) __nv_bfloat16 g_Kl[(size_t)NTOK*Hh];
__device__ __align__(16) __nv_bfloat16 g_Vh[(size_t)NTOK*Hh];
__device__ __align__(16) __nv_bfloat16 g_Vl[(size_t)NTOK*Hh];
// token-major [B,S,H] bf16 hi/lo (attention output)
__device__ __align__(16) __nv_bfloat16 g_Ch[(size_t)NTOK*Hh];
__device__ __align__(16) __nv_bfloat16 g_Cl[(size_t)NTOK*Hh];

// ---------------- PTX helpers (sm_80-class only; no 'a'-gated features) ----
__device__ __forceinline__ uint32_t smem_u32(const void* p) {
    uint32_t a;
    asm("{ .reg .u64 t; cvta.to.shared.u64 t, %1; cvt.u32.u64 %0, t; }" : "=r"(a) : "l"(p));
    return a;
}
__device__ __forceinline__ void cp16(uint32_t dst, const void* src, int valid) {
    int sz = valid ? 16 : 0;
    asm volatile("cp.async.cg.shared.global [%0], [%1], 16, %2;"
                 :: "r"(dst), "l"(src), "r"(sz) : "memory");
}
#define CP_COMMIT() asm volatile("cp.async.commit_group;" ::: "memory")
#define CP_WAIT0()  asm volatile("cp.async.wait_group 0;" ::: "memory")
#define CP_WAIT1()  asm volatile("cp.async.wait_group 1;" ::: "memory")
#define CP_WAIT2()  asm volatile("cp.async.wait_group 2;" ::: "memory")

#define LDM4(R, ADDR) \
    asm volatile("ldmatrix.sync.aligned.m8n8.x4.shared.b16 {%0,%1,%2,%3}, [%4];" \
        : "=r"((R)[0]), "=r"((R)[1]), "=r"((R)[2]), "=r"((R)[3]) : "r"(ADDR))
#define LDM4T(R, ADDR) \
    asm volatile("ldmatrix.sync.aligned.m8n8.x4.trans.shared.b16 {%0,%1,%2,%3}, [%4];" \
        : "=r"((R)[0]), "=r"((R)[1]), "=r"((R)[2]), "=r"((R)[3]) : "r"(ADDR))

#define MMA16816(D, A, B0, B1) \
    asm volatile("mma.sync.aligned.m16n8k16.row.col.f32.bf16.bf16.f32 " \
        "{%0,%1,%2,%3},{%4,%5,%6,%7},{%8,%9},{%0,%1,%2,%3};" \
        : "+f"((D)[0]), "+f"((D)[1]), "+f"((D)[2]), "+f"((D)[3]) \
        : "r"((A)[0]), "r"((A)[1]), "r"((A)[2]), "r"((A)[3]), "r"(B0), "r"(B1))

__device__ __forceinline__ uint32_t pack_bf16(float lo, float hi) {
    __nv_bfloat162 t = __float22bfloat162_rn(make_float2(lo, hi));
    return *(uint32_t*)&t;
}
__device__ __forceinline__ float bf16_res(float x) {
    return x - __bfloat162float(__float2bfloat16(x));
}

// ---------------- split fp32 -> bf16 hi/lo --------------------------------
__global__ __launch_bounds__(256)
void split_k(const float* __restrict__ x, __nv_bfloat16* __restrict__ hi,
             __nv_bfloat16* __restrict__ lo, int n)
{
    int i = (blockIdx.x * 256 + threadIdx.x) * 4;
    if (i >= n) return;
    float4 v = *(const float4*)(x + i);
    float f[4] = {v.x, v.y, v.z, v.w};
    union { __nv_bfloat16 b[4]; uint2 u; } ph, pl;
#pragma unroll
    for (int k = 0; k < 4; k++) {
        __nv_bfloat16 h = __float2bfloat16(f[k]);
        ph.b[k] = h;
        pl.b[k] = __float2bfloat16(f[k] - __bfloat162float(h));
    }
    *(uint2*)(hi + i) = ph.u;
    *(uint2*)(lo + i) = pl.u;
}

// ---------------- HMMA split-bf16 GEMM ------------------------------------
// out = A @ W^T + bias via 3 bf16 passes. CTA tile 256x128, K-chunk 32,
// 3-stage cp.async pipeline, 512 threads (16 warps = 4M x 4N, warp 64x32).
// smem rows at 80B pitch (5x16B) -> conflict-free ldmatrix.
// MODE 0: writes bf16 hi/lo head-major (scaled);  MODE 1: fp32 token-major.
#define AH_OFF   0
#define AL_OFF   20480                // 256*80
#define WH_OFF   40960
#define WL_OFF   51200                // + 128*80
#define STAGE_B  61440
#define SMEM_GEMM (3*STAGE_B)         // 184320 B

template<int MODE>
__global__ __launch_bounds__(512, 1)
void gemm_mma(const __nv_bfloat16* __restrict__ Ah, const __nv_bfloat16* __restrict__ Al,
              const __nv_bfloat16* __restrict__ Wh, const __nv_bfloat16* __restrict__ Wl,
              const float* __restrict__ bias,
              __nv_bfloat16* __restrict__ outh, __nv_bfloat16* __restrict__ outl,
              float* __restrict__ outf, float scale, int Nrows)
{
    extern __shared__ __align__(128) char smem[];
    const uint32_t sb = smem_u32(smem);
    const int tid  = threadIdx.x;
    const int wid  = tid >> 5;
    const int lane = tid & 31;
    const int n0 = blockIdx.x * 256;
    const int m0 = blockIdx.y * 128;
    const int warp_m = wid & 3;        // 4 groups of 64 rows
    const int warp_n = wid >> 2;       // 4 groups of 32 cols

    auto fill = [&](int chunk, int s) {
        const int k0 = chunk * 32;
        const uint32_t base = sb + (uint32_t)s * STAGE_B;
#pragma unroll
        for (int idx = tid; idx < 1024; idx += 512) {
            const int r = idx >> 2, c = idx & 3;
            const uint32_t dst = (uint32_t)(r * 5 + c) * 16;
            const int ar = n0 + r;
            const int av = (ar < Nrows);
            const size_t ao = (size_t)(av ? ar : 0) * 1024 + k0 + c * 8;
            cp16(base + AH_OFF + dst, Ah + ao, av);
            cp16(base + AL_OFF + dst, Al + ao, av);
        }
        {
            const int idx = tid;
            if (idx < 512) {
                const int r = idx >> 2, c = idx & 3;
                const uint32_t dst = (uint32_t)(r * 5 + c) * 16;
                const size_t wo = (size_t)(m0 + r) * 1024 + k0 + c * 8;
                cp16(base + WH_OFF + dst, Wh + wo, 1);
                cp16(base + WL_OFF + dst, Wl + wo, 1);
            }
        }
    };

    float acc[4][4][4];
#pragma unroll
    for (int i = 0; i < 4; i++)
#pragma unroll
        for (int j = 0; j < 4; j++)
#pragma unroll
            for (int d = 0; d < 4; d++) acc[i][j][d] = 0.f;

    const int rA = warp_m * 64 + (lane & 15);
    const int rW = warp_n * 32 + (lane & 15);
    const int hi16 = lane >> 4;

    fill(0, 0); CP_COMMIT();
    fill(1, 1); CP_COMMIT();

    int stage = 0;
    for (int ch = 0; ch < 32; ch++) {
        if (ch + 2 < 32) {
            int ns = stage + 2; if (ns >= 3) ns -= 3;
            fill(ch + 2, ns); CP_COMMIT();
            CP_WAIT2();
        } else if (ch == 30) {
            CP_WAIT1();
        } else {
            CP_WAIT0();
        }
        __syncthreads();

        const uint32_t base = sb + (uint32_t)stage * STAGE_B;
#pragma unroll
        for (int ks = 0; ks < 2; ks++) {
            const int c16 = ks * 2 + hi16;
            uint32_t bh[2][4], bl[2][4];
#pragma unroll
            for (int nb = 0; nb < 2; nb++) {
                const uint32_t off = (uint32_t)((rW + nb*16) * 5 + c16) * 16;
                LDM4(bh[nb], base + WH_OFF + off);
                LDM4(bl[nb], base + WL_OFF + off);
            }
#pragma unroll
            for (int ma = 0; ma < 4; ma++) {
                uint32_t ah[4], al[4];
                const uint32_t off = (uint32_t)((rA + ma*16) * 5 + c16) * 16;
                LDM4(ah, base + AH_OFF + off);
                LDM4(al, base + AL_OFF + off);
#pragma unroll
                for (int n8 = 0; n8 < 4; n8++) {
                    const int nb = n8 >> 1, h = n8 & 1;
                    MMA16816(acc[ma][n8], ah, bh[nb][0+h], bh[nb][2+h]);
                    MMA16816(acc[ma][n8], ah, bl[nb][0+h], bl[nb][2+h]);
                    MMA16816(acc[ma][n8], al, bh[nb][0+h], bh[nb][2+h]);
                }
            }
        }
        __syncthreads();
        if (++stage == 3) stage = 0;
    }

    float bias2[4][2];
#pragma unroll
    for (int n8 = 0; n8 < 4; n8++) {
        const int m = m0 + warp_n*32 + n8*8 + (lane & 3)*2;
        bias2[n8][0] = bias[m];
        bias2[n8][1] = bias[m + 1];
    }
#pragma unroll
    for (int ma = 0; ma < 4; ma++)
#pragma unroll
        for (int half = 0; half < 2; half++) {
            const int n = n0 + warp_m*64 + ma*16 + (lane >> 2) + half*8;
            if (n >= Nrows) continue;
#pragma unroll
            for (int n8 = 0; n8 < 4; n8++) {
                const int m = m0 + warp_n*32 + n8*8 + (lane & 3)*2;
                float vx = acc[ma][n8][2*half + 0] + bias2[n8][0];
                float vy = acc[ma][n8][2*half + 1] + bias2[n8][1];
                if (MODE == 0) {
                    vx *= scale; vy *= scale;
                    const int b = n / Ss, s = n - b * Ss;
                    const int h = m >> 6, d = m & 63;
                    const size_t off = (((size_t)(b*NH_ + h))*Ss + s)*DH_ + d;
                    *(uint32_t*)(outh + off) = pack_bf16(vx, vy);
                    *(uint32_t*)(outl + off) = pack_bf16(bf16_res(vx), bf16_res(vy));
                } else {
                    float2 v; v.x = vx; v.y = vy;
                    *(float2*)(outf + (size_t)n*1024 + m) = v;
                }
            }
        }
}

// ---------------------------------------------------------------------------
// HMMA flash attention. Grid (5, 512), 256 threads (8 warps x 16 q rows,
// q-tile 128). Split-bf16 3-pass for QK^T and PV. Multiplicative mask.
// Smem rows at 144B pitch ((r*9+c)%8 permutes -> conflict-free ldmatrix).
// ---------------------------------------------------------------------------
#define AP       9                    // 16B units per row
#define ATILE_B  (64*AP*16)           // 9216 B per 64x64 bf16 tile
#define QTILE_B  (128*AP*16)          // 18432 B per 128x64 bf16 tile
#define SM_Q     2560                 // after 640*4 mask bytes
#define SM_KV    (SM_Q + 2*QTILE_B)   // 2 stages x {Kh,Kl,Vh,Vl}
#define SMEM_ATT (SM_KV + 8*ATILE_B) // 113152 B

__global__ __launch_bounds__(256, 2)
void attn_mma(const float* __restrict__ mask,
              __nv_bfloat16* __restrict__ Ch, __nv_bfloat16* __restrict__ Cl)
{
    extern __shared__ __align__(128) char smem[];
    const uint32_t sb = smem_u32(smem);
    float* mask_s = (float*)smem;

    const int bh = blockIdx.y;
    const int b = bh >> 4, h = bh & 15;
    const int q0 = blockIdx.x * 128;
    const int tid = threadIdx.x;
    const int wid = tid >> 5;
    const int lane = tid & 31;

    const __nv_bfloat16* Qhg = g_Qh + (size_t)bh * Ss * DH_;
    const __nv_bfloat16* Qlg = g_Ql + (size_t)bh * Ss * DH_;
    const __nv_bfloat16* Khg = g_Kh + (size_t)bh * Ss * DH_;
    const __nv_bfloat16* Klg = g_Kl + (size_t)bh * Ss * DH_;
    const __nv_bfloat16* Vhg = g_Vh + (size_t)bh * Ss * DH_;
    const __nv_bfloat16* Vlg = g_Vl + (size_t)bh * Ss * DH_;

    // mask row -> smem (zero-padded to 640)
    for (int i = tid; i < 640; i += 256)
        mask_s[i] = (i < Ss) ? mask[b * Ss + i] : 0.f;

    // Q tiles (once): 128 rows x 64 bf16, hi/lo
#pragma unroll
    for (int idx = tid; idx < 1024; idx += 256) {
        const int r = idx >> 3, c = idx & 7;
        const uint32_t dst = (uint32_t)(r * AP + c) * 16;
        const int q = q0 + r;
        const int v = (q < Ss);
        const size_t off = (size_t)(v ? q : 0) * 64 + c * 8;
        cp16(sb + SM_Q + dst,           Qhg + off, v);
        cp16(sb + SM_Q + QTILE_B + dst, Qlg + off, v);
    }

    auto fillKV = [&](int kt, int s) {
        const int k0 = kt * 64;
        const uint32_t base = sb + SM_KV + (uint32_t)s * 4 * ATILE_B;
#pragma unroll
        for (int idx = tid; idx < 512; idx += 256) {
            const int r = idx >> 3, c = idx & 7;
            const uint32_t dst = (uint32_t)(r * AP + c) * 16;
            const int k = k0 + r;
            const int v = (k < Ss);
            const size_t off = (size_t)(v ? k : 0) * 64 + c * 8;
            cp16(base + dst,             Khg + off, v);
            cp16(base + ATILE_B + dst,   Klg + off, v);
            cp16(base + 2*ATILE_B + dst, Vhg + off, v);
            cp16(base + 3*ATILE_B + dst, Vlg + off, v);
        }
    };

    fillKV(0, 0); CP_COMMIT();

    float m0v = -1e30f, m1v = -1e30f, l0 = 0.f, l1 = 0.f;
    float ctx[8][4];
#pragma unroll
    for (int i = 0; i < 8; i++)
#pragma unroll
        for (int j = 0; j < 4; j++) ctx[i][j] = 0.f;

    const int rQ = wid * 16 + (lane & 15);
    const int hi16 = lane >> 4;

    for (int kt = 0; kt < 10; kt++) {
        __syncthreads();   // stage being overwritten fully consumed
        if (kt + 1 < 10) { fillKV(kt + 1, (kt + 1) & 1); CP_COMMIT(); CP_WAIT1(); }
        else             { CP_WAIT0(); }
        __syncthreads();

        const uint32_t base = sb + SM_KV + (uint32_t)(kt & 1) * 4 * ATILE_B;
        const uint32_t kHb = base, kLb = base + ATILE_B;
        const uint32_t vHb = base + 2*ATILE_B, vLb = base + 3*ATILE_B;

        // ---- scores = Q . K^T (3-pass split) ----
        float s[8][4];
#pragma unroll
        for (int i = 0; i < 8; i++)
#pragma unroll
            for (int j = 0; j < 4; j++) s[i][j] = 0.f;

#pragma unroll
        for (int kk = 0; kk < 4; kk++) {
            const int c16 = kk * 2 + hi16;
            uint32_t qh[4], ql[4];
            const uint32_t qoff = (uint32_t)(rQ * AP + c16) * 16;
            LDM4(qh, sb + SM_Q + qoff);
            LDM4(ql, sb + SM_Q + QTILE_B + qoff);
#pragma unroll
            for (int nb = 0; nb < 4; nb++) {
                uint32_t kh[4], kl[4];
                const uint32_t koff = (uint32_t)((nb*16 + (lane & 15)) * AP + c16) * 16;
                LDM4(kh, kHb + koff);
                LDM4(kl, kLb + koff);
#pragma unroll
                for (int hh = 0; hh < 2; hh++) {
                    MMA16816(s[2*nb+hh], qh, kh[0+hh], kh[2+hh]);
                    MMA16816(s[2*nb+hh], qh, kl[0+hh], kl[2+hh]);
                    MMA16816(s[2*nb+hh], ql, kh[0+hh], kh[2+hh]);
                }
            }
        }

        // ---- multiplicative mask + key padding ----
        const int k0 = kt * 64;
#pragma unroll
        for (int n8 = 0; n8 < 8; n8++) {
            const int kb = k0 + n8*8 + 2*(lane & 3);
            const float mA = mask_s[kb], mB = mask_s[kb + 1];
            const bool okA = (kb < Ss), okB = (kb + 1 < Ss);
            s[n8][0] = okA ? s[n8][0]*mA : -1e30f;
            s[n8][1] = okB ? s[n8][1]*mB : -1e30f;
            s[n8][2] = okA ? s[n8][2]*mA : -1e30f;
            s[n8][3] = okB ? s[n8][3]*mB : -1e30f;
        }

        // ---- online softmax (rows r0=lane>>2, r1=r0+8; reduce over lane&3) ----
        float tm0 = -1e30f, tm1 = -1e30f;
#pragma unroll
        for (int n8 = 0; n8 < 8; n8++) {
            tm0 = fmaxf(tm0, fmaxf(s[n8][0], s[n8][1]));
            tm1 = fmaxf(tm1, fmaxf(s[n8][2], s[n8][3]));
        }
#pragma unroll
        for (int o = 1; o <= 2; o <<= 1) {
            tm0 = fmaxf(tm0, __shfl_xor_sync(0xffffffffu, tm0, o));
            tm1 = fmaxf(tm1, __shfl_xor_sync(0xffffffffu, tm1, o));
        }
        const float mn0 = fmaxf(m0v, tm0), mn1 = fmaxf(m1v, tm1);
        const float c0 = __expf(m0v - mn0), c1 = __expf(m1v - mn1);
        float rs0 = 0.f, rs1 = 0.f;
#pragma unroll
        for (int n8 = 0; n8 < 8; n8++) {
            s[n8][0] = __expf(s[n8][0] - mn0); rs0 += s[n8][0];
            s[n8][1] = __expf(s[n8][1] - mn0); rs0 += s[n8][1];
            s[n8][2] = __expf(s[n8][2] - mn1); rs1 += s[n8][2];
            s[n8][3] = __expf(s[n8][3] - mn1); rs1 += s[n8][3];
        }
#pragma unroll
        for (int o = 1; o <= 2; o <<= 1) {
            rs0 += __shfl_xor_sync(0xffffffffu, rs0, o);
            rs1 += __shfl_xor_sync(0xffffffffu, rs1, o);
        }
        l0 = l0*c0 + rs0; l1 = l1*c1 + rs1;
        m0v = mn0; m1v = mn1;
#pragma unroll
        for (int n8 = 0; n8 < 8; n8++) {
            ctx[n8][0] *= c0; ctx[n8][1] *= c0;
            ctx[n8][2] *= c1; ctx[n8][3] *= c1;
        }

        // ---- ctx += P @ V (3-pass split; P frags reused from s regs) ----
#pragma unroll
        for (int t = 0; t < 4; t++) {
            uint32_t ph[4], pl[4];
            ph[0] = pack_bf16(s[2*t][0],   s[2*t][1]);
            ph[1] = pack_bf16(s[2*t][2],   s[2*t][3]);
            ph[2] = pack_bf16(s[2*t+1][0], s[2*t+1][1]);
            ph[3] = pack_bf16(s[2*t+1][2], s[2*t+1][3]);
            pl[0] = pack_bf16(bf16_res(s[2*t][0]),   bf16_res(s[2*t][1]));
            pl[1] = pack_bf16(bf16_res(s[2*t][2]),   bf16_res(s[2*t][3]));
            pl[2] = pack_bf16(bf16_res(s[2*t+1][0]), bf16_res(s[2*t+1][1]));
            pl[3] = pack_bf16(bf16_res(s[2*t+1][2]), bf16_res(s[2*t+1][3]));
#pragma unroll
            for (int g = 0; g < 4; g++) {
                uint32_t vh[4], vl[4];
                const uint32_t voff = (uint32_t)((t*16 + (lane & 15)) * AP + g*2 + hi16) * 16;
                LDM4T(vh, vHb + voff);
                LDM4T(vl, vLb + voff);
#pragma unroll
                for (int hh = 0; hh < 2; hh++) {
                    MMA16816(ctx[2*g+hh], ph, vh[2*hh], vh[2*hh+1]);
                    MMA16816(ctx[2*g+hh], ph, vl[2*hh], vl[2*hh+1]);
                    MMA16816(ctx[2*g+hh], pl, vh[2*hh], vh[2*hh+1]);
                }
            }
        }
    }

    // ---- epilogue: bf16 hi/lo token-major [B,S,H] ----
    const float i0 = 1.f / l0, i1 = 1.f / l1;
    const int qr = q0 + wid*16 + (lane >> 2);
    const int d0 = 2*(lane & 3);
#pragma unroll
    for (int n8 = 0; n8 < 8; n8++) {
        const int d = h*64 + n8*8 + d0;
        if (qr < Ss) {
            const float vx = ctx[n8][0]*i0, vy = ctx[n8][1]*i0;
            const size_t off = ((size_t)(b*Ss + qr))*Hh + d;
            *(uint32_t*)(Ch + off) = pack_bf16(vx, vy);
            *(uint32_t*)(Cl + off) = pack_bf16(bf16_res(vx), bf16_res(vy));
        }
        if (qr + 8 < Ss) {
            const float vx = ctx[n8][2]*i1, vy = ctx[n8][3]*i1;
            const size_t off = ((size_t)(b*Ss + qr + 8))*Hh + d;
            *(uint32_t*)(Ch + off) = pack_bf16(vx, vy);
            *(uint32_t*)(Cl + off) = pack_bf16(bf16_res(vx), bf16_res(vy));
        }
    }
}

// ---------------------------------------------------------------------------
extern "C" void kernel_launch(void* const* d_in, const int* in_sizes, int n_in,
                              void* d_out, int out_size)
{
    const float* X    = (const float*)d_in[0];
    const float* mask = (const float*)d_in[1];
    const float* Wq   = (const float*)d_in[2];
    const float* bq   = (const float*)d_in[3];
    const float* Wk   = (const float*)d_in[4];
    const float* bk   = (const float*)d_in[5];
    const float* Wv   = (const float*)d_in[6];
    const float* bv   = (const float*)d_in[7];
    const float* Wo   = (const float*)d_in[8];
    const float* bo   = (const float*)d_in[9];
    float* out = (float*)d_out;

    __nv_bfloat16 *Xh, *Xl, *Wh, *Wl, *Qh, *Ql, *Kh, *Kl, *Vh, *Vl, *Ch, *Cl;
    cudaGetSymbolAddress((void**)&Xh, g_Xh);
    cudaGetSymbolAddress((void**)&Xl, g_Xl);
    cudaGetSymbolAddress((void**)&Wh, g_Wh);
    cudaGetSymbolAddress((void**)&Wl, g_Wl);
    cudaGetSymbolAddress((void**)&Qh, g_Qh);
    cudaGetSymbolAddress((void**)&Ql, g_Ql);
    cudaGetSymbolAddress((void**)&Kh, g_Kh);
    cudaGetSymbolAddress((void**)&Kl, g_Kl);
    cudaGetSymbolAddress((void**)&Vh, g_Vh);
    cudaGetSymbolAddress((void**)&Vl, g_Vl);
    cudaGetSymbolAddress((void**)&Ch, g_Ch);
    cudaGetSymbolAddress((void**)&Cl, g_Cl);

    static bool attr_done = false;
    if (!attr_done) {
        cudaFuncSetAttribute(gemm_mma<0>, cudaFuncAttributeMaxDynamicSharedMemorySize, SMEM_GEMM);
        cudaFuncSetAttribute(gemm_mma<1>, cudaFuncAttributeMaxDynamicSharedMemorySize, SMEM_GEMM);
        cudaFuncSetAttribute(attn_mma, cudaFuncAttributeMaxDynamicSharedMemorySize, SMEM_ATT);
        attr_done = true;
    }

    // split inputs to bf16 hi/lo
    split_k<<<NTOK, 256>>>(X, Xh, Xl, NTOK * Hh);
    const float* Ws[4] = {Wq, Wk, Wv, Wo};
    for (int w = 0; w < 4; w++)
        split_k<<<1024, 256>>>(Ws[w], Wh + (size_t)w*Hh*Hh, Wl + (size_t)w*Hh*Hh, Hh*Hh);

    const dim3 gg((NTOK + 255) / 256, Hh / 128);
    // Q pre-scaled by 1/sqrt(DH)=0.125
    gemm_mma<0><<<gg, 512, SMEM_GEMM>>>(Xh, Xl, Wh + 0*(size_t)Hh*Hh, Wl + 0*(size_t)Hh*Hh,
                                        bq, Qh, Ql, nullptr, 0.125f, NTOK);
    gemm_mma<0><<<gg, 512, SMEM_GEMM>>>(Xh, Xl, Wh + 1*(size_t)Hh*Hh, Wl + 1*(size_t)Hh*Hh,
                                        bk, Kh, Kl, nullptr, 1.0f, NTOK);
    gemm_mma<0><<<gg, 512, SMEM_GEMM>>>(Xh, Xl, Wh + 2*(size_t)Hh*Hh, Wl + 2*(size_t)Hh*Hh,
                                        bv, Vh, Vl, nullptr, 1.0f, NTOK);

    attn_mma<<<dim3((Ss + 127) / 128, Bb * NH_), 256, SMEM_ATT>>>(mask, Ch, Cl);

    gemm_mma<1><<<gg, 512, SMEM_GEMM>>>(Ch, Cl, Wh + 3*(size_t)Hh*Hh, Wl + 3*(size_t)Hh*Hh,
                                        bo, nullptr, nullptr, out, 1.0f, NTOK);
}

// round 16
// speedup vs baseline: 1.0187x; 1.0187x over previous
#include <cuda_runtime.h>
#include <cuda_bf16.h>
#include <math.h>
#include <stdint.h>

#define Bb   32
#define Ss   577
#define Hh   1024
#define NH_  16
#define DH_  64
#define NTOK (Bb*Ss)          // 18464

// ---------------- scratch (__device__ globals; no allocs allowed) ----------
__device__ __align__(16) __nv_bfloat16 g_Xh[(size_t)NTOK*Hh];
__device__ __align__(16) __nv_bfloat16 g_Xl[(size_t)NTOK*Hh];
__device__ __align__(16) __nv_bfloat16 g_Wh[(size_t)4*Hh*Hh];
__device__ __align__(16) __nv_bfloat16 g_Wl[(size_t)4*Hh*Hh];
// head-major [B,NH,S,DH] bf16 hi/lo
__device__ __align__(16) __nv_bfloat16 g_Qh[(size_t)NTOK*Hh];
__device__ __align__(16) __nv_bfloat16 g_Ql[(size_t)NTOK*Hh];
__device__ __align__(16) __nv_bfloat16 g_Kh[(size_t)NTOK*Hh];
__device__ __align__(16) __nv_bfloat16 g_Kl[(size_t)NTOK*Hh];
__device__ __align__(16) __nv_bfloat16 g_Vh[(size_t)NTOK*Hh];
__device__ __align__(16) __nv_bfloat16 g_Vl[(size_t)NTOK*Hh];
// token-major [B,S,H] bf16 hi/lo (attention output)
__device__ __align__(16) __nv_bfloat16 g_Ch[(size_t)NTOK*Hh];
__device__ __align__(16) __nv_bfloat16 g_Cl[(size_t)NTOK*Hh];

// ---------------- PTX helpers (sm_80-class only; no 'a'-gated features) ----
__device__ __forceinline__ uint32_t smem_u32(const void* p) {
    uint32_t a;
    asm("{ .reg .u64 t; cvta.to.shared.u64 t, %1; cvt.u32.u64 %0, t; }" : "=r"(a) : "l"(p));
    return a;
}
__device__ __forceinline__ void cp16(uint32_t dst, const void* src, int valid) {
    int sz = valid ? 16 : 0;
    asm volatile("cp.async.cg.shared.global [%0], [%1], 16, %2;"
                 :: "r"(dst), "l"(src), "r"(sz) : "memory");
}
#define CP_COMMIT() asm volatile("cp.async.commit_group;" ::: "memory")
#define CP_WAIT0()  asm volatile("cp.async.wait_group 0;" ::: "memory")
#define CP_WAIT1()  asm volatile("cp.async.wait_group 1;" ::: "memory")

#define LDM4(R, ADDR) \
    asm volatile("ldmatrix.sync.aligned.m8n8.x4.shared.b16 {%0,%1,%2,%3}, [%4];" \
        : "=r"((R)[0]), "=r"((R)[1]), "=r"((R)[2]), "=r"((R)[3]) : "r"(ADDR))
#define LDM4T(R, ADDR) \
    asm volatile("ldmatrix.sync.aligned.m8n8.x4.trans.shared.b16 {%0,%1,%2,%3}, [%4];" \
        : "=r"((R)[0]), "=r"((R)[1]), "=r"((R)[2]), "=r"((R)[3]) : "r"(ADDR))

#define MMA16816(D, A, B0, B1) \
    asm volatile("mma.sync.aligned.m16n8k16.row.col.f32.bf16.bf16.f32 " \
        "{%0,%1,%2,%3},{%4,%5,%6,%7},{%8,%9},{%0,%1,%2,%3};" \
        : "+f"((D)[0]), "+f"((D)[1]), "+f"((D)[2]), "+f"((D)[3]) \
        : "r"((A)[0]), "r"((A)[1]), "r"((A)[2]), "r"((A)[3]), "r"(B0), "r"(B1))

__device__ __forceinline__ uint32_t pack_bf16(float lo, float hi) {
    __nv_bfloat162 t = __float22bfloat162_rn(make_float2(lo, hi));
    return *(uint32_t*)&t;
}
__device__ __forceinline__ float bf16_res(float x) {
    return x - __bfloat162float(__float2bfloat16(x));
}

// ---------------- split fp32 -> bf16 hi/lo --------------------------------
__global__ __launch_bounds__(256)
void split_k(const float* __restrict__ x, __nv_bfloat16* __restrict__ hi,
             __nv_bfloat16* __restrict__ lo, int n)
{
    int i = (blockIdx.x * 256 + threadIdx.x) * 4;
    if (i >= n) return;
    float4 v = *(const float4*)(x + i);
    float f[4] = {v.x, v.y, v.z, v.w};
    union { __nv_bfloat16 b[4]; uint2 u; } ph, pl;
#pragma unroll
    for (int k = 0; k < 4; k++) {
        __nv_bfloat16 h = __float2bfloat16(f[k]);
        ph.b[k] = h;
        pl.b[k] = __float2bfloat16(f[k] - __bfloat162float(h));
    }
    *(uint2*)(hi + i) = ph.u;
    *(uint2*)(lo + i) = pl.u;
}

// ---------------- HMMA split-bf16 GEMM ------------------------------------
// out = A @ W^T + bias via 3 bf16 passes. CTA tile 128x128, K-chunk 32,
// 2-stage cp.async, 256 threads (8 warps = 2M x 4N), register-lean inner
// loop (B frags hoisted per k-step, A streamed) -> 2 CTAs/SM.
// smem rows at 80B pitch (5x16B) -> conflict-free ldmatrix.
// MODE 0: writes bf16 hi/lo head-major (scaled);  MODE 1: fp32 token-major.
#define TILE_B   (128*5*16)           // 10240 B per operand tile
#define SMEM_GEMM (8*TILE_B)          // 2 stages x 4 tiles = 81920 B

template<int MODE>
__global__ __launch_bounds__(256, 2)
void gemm_mma(const __nv_bfloat16* __restrict__ Ah, const __nv_bfloat16* __restrict__ Al,
              const __nv_bfloat16* __restrict__ Wh, const __nv_bfloat16* __restrict__ Wl,
              const float* __restrict__ bias,
              __nv_bfloat16* __restrict__ outh, __nv_bfloat16* __restrict__ outl,
              float* __restrict__ outf, float scale, int Nrows)
{
    extern __shared__ __align__(128) char smem[];
    const uint32_t sb = smem_u32(smem);
    const int tid  = threadIdx.x;
    const int wid  = tid >> 5;
    const int lane = tid & 31;
    const int n0 = blockIdx.x * 128;
    const int m0 = blockIdx.y * 128;
    const int warp_m = wid & 1;
    const int warp_n = wid >> 1;

    auto fill = [&](int chunk, int s) {
        const int k0 = chunk * 32;
        const uint32_t base = sb + s * 4 * TILE_B;
#pragma unroll
        for (int idx = tid; idx < 512; idx += 256) {
            const int r = idx >> 2, c = idx & 3;
            const uint32_t dst = (uint32_t)(r * 5 + c) * 16;
            const int ar = n0 + r;
            const int av = (ar < Nrows);
            const size_t ao = (size_t)(av ? ar : 0) * 1024 + k0 + c * 8;
            cp16(base + dst,              Ah + ao, av);
            cp16(base + TILE_B + dst,     Al + ao, av);
            const size_t wo = (size_t)(m0 + r) * 1024 + k0 + c * 8;
            cp16(base + 2*TILE_B + dst,   Wh + wo, 1);
            cp16(base + 3*TILE_B + dst,   Wl + wo, 1);
        }
    };

    float acc[4][4][4];
#pragma unroll
    for (int i = 0; i < 4; i++)
#pragma unroll
        for (int j = 0; j < 4; j++)
#pragma unroll
            for (int d = 0; d < 4; d++) acc[i][j][d] = 0.f;

    const int rA = warp_m * 64 + (lane & 15);
    const int rW = warp_n * 32 + (lane & 15);
    const int hi16 = lane >> 4;

    fill(0, 0); CP_COMMIT();

    for (int ch = 0; ch < 32; ch++) {
        if (ch + 1 < 32) { fill(ch + 1, (ch + 1) & 1); CP_COMMIT(); CP_WAIT1(); }
        else             { CP_WAIT0(); }
        __syncthreads();

        const uint32_t base = sb + (ch & 1) * 4 * TILE_B;
#pragma unroll
        for (int ks = 0; ks < 2; ks++) {
            const int c16 = ks * 2 + hi16;
            uint32_t bh[2][4], bl[2][4];
#pragma unroll
            for (int nb = 0; nb < 2; nb++) {
                const uint32_t off = (uint32_t)((rW + nb*16) * 5 + c16) * 16;
                LDM4(bh[nb], base + 2*TILE_B + off);
                LDM4(bl[nb], base + 3*TILE_B + off);
            }
#pragma unroll
            for (int ma = 0; ma < 4; ma++) {
                uint32_t ah[4], al[4];
                const uint32_t off = (uint32_t)((rA + ma*16) * 5 + c16) * 16;
                LDM4(ah, base + off);
                LDM4(al, base + TILE_B + off);
#pragma unroll
                for (int n8 = 0; n8 < 4; n8++) {
                    const int nb = n8 >> 1, h = n8 & 1;
                    MMA16816(acc[ma][n8], ah, bh[nb][0+h], bh[nb][2+h]);
                    MMA16816(acc[ma][n8], ah, bl[nb][0+h], bl[nb][2+h]);
                    MMA16816(acc[ma][n8], al, bh[nb][0+h], bh[nb][2+h]);
                }
            }
        }
        __syncthreads();
    }

    float bias2[4][2];
#pragma unroll
    for (int n8 = 0; n8 < 4; n8++) {
        const int m = m0 + warp_n*32 + n8*8 + (lane & 3)*2;
        bias2[n8][0] = bias[m];
        bias2[n8][1] = bias[m + 1];
    }
#pragma unroll
    for (int ma = 0; ma < 4; ma++)
#pragma unroll
        for (int half = 0; half < 2; half++) {
            const int n = n0 + warp_m*64 + ma*16 + (lane >> 2) + half*8;
            if (n >= Nrows) continue;
#pragma unroll
            for (int n8 = 0; n8 < 4; n8++) {
                const int m = m0 + warp_n*32 + n8*8 + (lane & 3)*2;
                float vx = acc[ma][n8][2*half + 0] + bias2[n8][0];
                float vy = acc[ma][n8][2*half + 1] + bias2[n8][1];
                if (MODE == 0) {
                    vx *= scale; vy *= scale;
                    const int b = n / Ss, s = n - b * Ss;
                    const int h = m >> 6, d = m & 63;
                    const size_t off = (((size_t)(b*NH_ + h))*Ss + s)*DH_ + d;
                    *(uint32_t*)(outh + off) = pack_bf16(vx, vy);
                    *(uint32_t*)(outl + off) = pack_bf16(bf16_res(vx), bf16_res(vy));
                } else {
                    float2 v; v.x = vx; v.y = vy;
                    *(float2*)(outf + (size_t)n*1024 + m) = v;
                }
            }
        }
}

// ---------------------------------------------------------------------------
// HMMA flash attention. Grid (10, 512), 128 threads (4 warps x 16 q rows).
// Split-bf16 3-pass for QK^T and PV. Multiplicative mask (ref semantics).
// Smem rows at 144B pitch ((r*9+c)%8 permutes -> conflict-free ldmatrix).
// launch_bounds(128,2): cap regs at 128 so 2 CTAs/SM co-reside.
// ---------------------------------------------------------------------------
#define AP       9                    // 16B units per row
#define ATILE_B  (64*AP*16)           // 9216 B per 64x64 bf16 tile
#define SM_Q     2560                 // Qh, Ql
#define SM_KV    (2560 + 2*ATILE_B)   // 2 stages x {Kh,Kl,Vh,Vl}
#define SMEM_ATT (SM_KV + 8*ATILE_B)  // 94720 B

__global__ __launch_bounds__(128, 2)
void attn_mma(const float* __restrict__ mask,
              __nv_bfloat16* __restrict__ Ch, __nv_bfloat16* __restrict__ Cl)
{
    extern __shared__ __align__(128) char smem[];
    const uint32_t sb = smem_u32(smem);
    float* mask_s = (float*)smem;

    const int bh = blockIdx.y;
    const int b = bh >> 4, h = bh & 15;
    const int q0 = blockIdx.x * 64;
    const int tid = threadIdx.x;
    const int wid = tid >> 5;
    const int lane = tid & 31;

    const __nv_bfloat16* Qhg = g_Qh + (size_t)bh * Ss * DH_;
    const __nv_bfloat16* Qlg = g_Ql + (size_t)bh * Ss * DH_;
    const __nv_bfloat16* Khg = g_Kh + (size_t)bh * Ss * DH_;
    const __nv_bfloat16* Klg = g_Kl + (size_t)bh * Ss * DH_;
    const __nv_bfloat16* Vhg = g_Vh + (size_t)bh * Ss * DH_;
    const __nv_bfloat16* Vlg = g_Vl + (size_t)bh * Ss * DH_;

    // mask row -> smem (zero-padded to 640)
    for (int i = tid; i < 640; i += 128)
        mask_s[i] = (i < Ss) ? mask[b * Ss + i] : 0.f;

    // Q tiles (once)
    for (int idx = tid; idx < 512; idx += 128) {
        const int r = idx >> 3, c = idx & 7;
        const uint32_t dst = (uint32_t)(r * AP + c) * 16;
        const int q = q0 + r;
        const int v = (q < Ss);
        const size_t off = (size_t)(v ? q : 0) * 64 + c * 8;
        cp16(sb + SM_Q + dst,           Qhg + off, v);
        cp16(sb + SM_Q + ATILE_B + dst, Qlg + off, v);
    }

    auto fillKV = [&](int kt, int s) {
        const int k0 = kt * 64;
        const uint32_t base = sb + SM_KV + s * 4 * ATILE_B;
        for (int idx = tid; idx < 512; idx += 128) {
            const int r = idx >> 3, c = idx & 7;
            const uint32_t dst = (uint32_t)(r * AP + c) * 16;
            const int k = k0 + r;
            const int v = (k < Ss);
            const size_t off = (size_t)(v ? k : 0) * 64 + c * 8;
            cp16(base + dst,             Khg + off, v);
            cp16(base + ATILE_B + dst,   Klg + off, v);
            cp16(base + 2*ATILE_B + dst, Vhg + off, v);
            cp16(base + 3*ATILE_B + dst, Vlg + off, v);
        }
    };

    fillKV(0, 0); CP_COMMIT();

    float m0v = -1e30f, m1v = -1e30f, l0 = 0.f, l1 = 0.f;
    float ctx[8][4];
#pragma unroll
    for (int i = 0; i < 8; i++)
#pragma unroll
        for (int j = 0; j < 4; j++) ctx[i][j] = 0.f;

    const int rQ = wid * 16 + (lane & 15);
    const int hi16 = lane >> 4;

    for (int kt = 0; kt < 10; kt++) {
        __syncthreads();   // stage being overwritten fully consumed
        if (kt + 1 < 10) { fillKV(kt + 1, (kt + 1) & 1); CP_COMMIT(); CP_WAIT1(); }
        else             { CP_WAIT0(); }
        __syncthreads();

        const uint32_t base = sb + SM_KV + (kt & 1) * 4 * ATILE_B;
        const uint32_t kHb = base, kLb = base + ATILE_B;
        const uint32_t vHb = base + 2*ATILE_B, vLb = base + 3*ATILE_B;

        // ---- scores = Q . K^T (3-pass split) ----
        float s[8][4];
#pragma unroll
        for (int i = 0; i < 8; i++)
#pragma unroll
            for (int j = 0; j < 4; j++) s[i][j] = 0.f;

#pragma unroll
        for (int kk = 0; kk < 4; kk++) {
            const int c16 = kk * 2 + hi16;
            uint32_t qh[4], ql[4];
            const uint32_t qoff = (uint32_t)(rQ * AP + c16) * 16;
            LDM4(qh, sb + SM_Q + qoff);
            LDM4(ql, sb + SM_Q + ATILE_B + qoff);
#pragma unroll
            for (int nb = 0; nb < 4; nb++) {
                uint32_t kh[4], kl[4];
                const uint32_t koff = (uint32_t)((nb*16 + (lane & 15)) * AP + c16) * 16;
                LDM4(kh, kHb + koff);
                LDM4(kl, kLb + koff);
#pragma unroll
                for (int hh = 0; hh < 2; hh++) {
                    MMA16816(s[2*nb+hh], qh, kh[0+hh], kh[2+hh]);
                    MMA16816(s[2*nb+hh], qh, kl[0+hh], kl[2+hh]);
                    MMA16816(s[2*nb+hh], ql, kh[0+hh], kh[2+hh]);
                }
            }
        }

        // ---- multiplicative mask + key padding ----
        const int k0 = kt * 64;
#pragma unroll
        for (int n8 = 0; n8 < 8; n8++) {
            const int kb = k0 + n8*8 + 2*(lane & 3);
            const float mA = mask_s[kb], mB = mask_s[kb + 1];
            const bool okA = (kb < Ss), okB = (kb + 1 < Ss);
            s[n8][0] = okA ? s[n8][0]*mA : -1e30f;
            s[n8][1] = okB ? s[n8][1]*mB : -1e30f;
            s[n8][2] = okA ? s[n8][2]*mA : -1e30f;
            s[n8][3] = okB ? s[n8][3]*mB : -1e30f;
        }

        // ---- online softmax (rows r0=lane>>2, r1=r0+8; reduce over lane&3) ----
        float tm0 = -1e30f, tm1 = -1e30f;
#pragma unroll
        for (int n8 = 0; n8 < 8; n8++) {
            tm0 = fmaxf(tm0, fmaxf(s[n8][0], s[n8][1]));
            tm1 = fmaxf(tm1, fmaxf(s[n8][2], s[n8][3]));
        }
#pragma unroll
        for (int o = 1; o <= 2; o <<= 1) {
            tm0 = fmaxf(tm0, __shfl_xor_sync(0xffffffffu, tm0, o));
            tm1 = fmaxf(tm1, __shfl_xor_sync(0xffffffffu, tm1, o));
        }
        const float mn0 = fmaxf(m0v, tm0), mn1 = fmaxf(m1v, tm1);
        const float c0 = __expf(m0v - mn0), c1 = __expf(m1v - mn1);
        float rs0 = 0.f, rs1 = 0.f;
#pragma unroll
        for (int n8 = 0; n8 < 8; n8++) {
            s[n8][0] = __expf(s[n8][0] - mn0); rs0 += s[n8][0];
            s[n8][1] = __expf(s[n8][1] - mn0); rs0 += s[n8][1];
            s[n8][2] = __expf(s[n8][2] - mn1); rs1 += s[n8][2];
            s[n8][3] = __expf(s[n8][3] - mn1); rs1 += s[n8][3];
        }
#pragma unroll
        for (int o = 1; o <= 2; o <<= 1) {
            rs0 += __shfl_xor_sync(0xffffffffu, rs0, o);
            rs1 += __shfl_xor_sync(0xffffffffu, rs1, o);
        }
        l0 = l0*c0 + rs0; l1 = l1*c1 + rs1;
        m0v = mn0; m1v = mn1;
#pragma unroll
        for (int n8 = 0; n8 < 8; n8++) {
            ctx[n8][0] *= c0; ctx[n8][1] *= c0;
            ctx[n8][2] *= c1; ctx[n8][3] *= c1;
        }

        // ---- ctx += P @ V (3-pass split; P frags reused from s regs) ----
#pragma unroll
        for (int t = 0; t < 4; t++) {
            uint32_t ph[4], pl[4];
            ph[0] = pack_bf16(s[2*t][0],   s[2*t][1]);
            ph[1] = pack_bf16(s[2*t][2],   s[2*t][3]);
            ph[2] = pack_bf16(s[2*t+1][0], s[2*t+1][1]);
            ph[3] = pack_bf16(s[2*t+1][2], s[2*t+1][3]);
            pl[0] = pack_bf16(bf16_res(s[2*t][0]),   bf16_res(s[2*t][1]));
            pl[1] = pack_bf16(bf16_res(s[2*t][2]),   bf16_res(s[2*t][3]));
            pl[2] = pack_bf16(bf16_res(s[2*t+1][0]), bf16_res(s[2*t+1][1]));
            pl[3] = pack_bf16(bf16_res(s[2*t+1][2]), bf16_res(s[2*t+1][3]));
#pragma unroll
            for (int g = 0; g < 4; g++) {
                uint32_t vh[4], vl[4];
                const uint32_t voff = (uint32_t)((t*16 + (lane & 15)) * AP + g*2 + hi16) * 16;
                LDM4T(vh, vHb + voff);
                LDM4T(vl, vLb + voff);
#pragma unroll
                for (int hh = 0; hh < 2; hh++) {
                    MMA16816(ctx[2*g+hh], ph, vh[2*hh], vh[2*hh+1]);
                    MMA16816(ctx[2*g+hh], ph, vl[2*hh], vl[2*hh+1]);
                    MMA16816(ctx[2*g+hh], pl, vh[2*hh], vh[2*hh+1]);
                }
            }
        }
    }

    // ---- epilogue: bf16 hi/lo token-major [B,S,H] ----
    const float i0 = 1.f / l0, i1 = 1.f / l1;
    const int qr = q0 + wid*16 + (lane >> 2);
    const int d0 = 2*(lane & 3);
#pragma unroll
    for (int n8 = 0; n8 < 8; n8++) {
        const int d = h*64 + n8*8 + d0;
        if (qr < Ss) {
            const float vx = ctx[n8][0]*i0, vy = ctx[n8][1]*i0;
            const size_t off = ((size_t)(b*Ss + qr))*Hh + d;
            *(uint32_t*)(Ch + off) = pack_bf16(vx, vy);
            *(uint32_t*)(Cl + off) = pack_bf16(bf16_res(vx), bf16_res(vy));
        }
        if (qr + 8 < Ss) {
            const float vx = ctx[n8][2]*i1, vy = ctx[n8][3]*i1;
            const size_t off = ((size_t)(b*Ss + qr + 8))*Hh + d;
            *(uint32_t*)(Ch + off) = pack_bf16(vx, vy);
            *(uint32_t*)(Cl + off) = pack_bf16(bf16_res(vx), bf16_res(vy));
        }
    }
}

// ---------------------------------------------------------------------------
extern "C" void kernel_launch(void* const* d_in, const int* in_sizes, int n_in,
                              void* d_out, int out_size)
{
    const float* X    = (const float*)d_in[0];
    const float* mask = (const float*)d_in[1];
    const float* Wq   = (const float*)d_in[2];
    const float* bq   = (const float*)d_in[3];
    const float* Wk   = (const float*)d_in[4];
    const float* bk   = (const float*)d_in[5];
    const float* Wv   = (const float*)d_in[6];
    const float* bv   = (const float*)d_in[7];
    const float* Wo   = (const float*)d_in[8];
    const float* bo   = (const float*)d_in[9];
    float* out = (float*)d_out;

    __nv_bfloat16 *Xh, *Xl, *Wh, *Wl, *Qh, *Ql, *Kh, *Kl, *Vh, *Vl, *Ch, *Cl;
    cudaGetSymbolAddress((void**)&Xh, g_Xh);
    cudaGetSymbolAddress((void**)&Xl, g_Xl);
    cudaGetSymbolAddress((void**)&Wh, g_Wh);
    cudaGetSymbolAddress((void**)&Wl, g_Wl);
    cudaGetSymbolAddress((void**)&Qh, g_Qh);
    cudaGetSymbolAddress((void**)&Ql, g_Ql);
    cudaGetSymbolAddress((void**)&Kh, g_Kh);
    cudaGetSymbolAddress((void**)&Kl, g_Kl);
    cudaGetSymbolAddress((void**)&Vh, g_Vh);
    cudaGetSymbolAddress((void**)&Vl, g_Vl);
    cudaGetSymbolAddress((void**)&Ch, g_Ch);
    cudaGetSymbolAddress((void**)&Cl, g_Cl);

    static bool attr_done = false;
    if (!attr_done) {
        cudaFuncSetAttribute(gemm_mma<0>, cudaFuncAttributeMaxDynamicSharedMemorySize, SMEM_GEMM);
        cudaFuncSetAttribute(gemm_mma<1>, cudaFuncAttributeMaxDynamicSharedMemorySize, SMEM_GEMM);
        cudaFuncSetAttribute(attn_mma, cudaFuncAttributeMaxDynamicSharedMemorySize, SMEM_ATT);
        attr_done = true;
    }

    // split inputs to bf16 hi/lo
    split_k<<<NTOK, 256>>>(X, Xh, Xl, NTOK * Hh);
    const float* Ws[4] = {Wq, Wk, Wv, Wo};
    for (int w = 0; w < 4; w++)
        split_k<<<1024, 256>>>(Ws[w], Wh + (size_t)w*Hh*Hh, Wl + (size_t)w*Hh*Hh, Hh*Hh);

    const dim3 gg((NTOK + 127) / 128, Hh / 128);
    // Q pre-scaled by 1/sqrt(DH)=0.125
    gemm_mma<0><<<gg, 256, SMEM_GEMM>>>(Xh, Xl, Wh + 0*(size_t)Hh*Hh, Wl + 0*(size_t)Hh*Hh,
                                        bq, Qh, Ql, nullptr, 0.125f, NTOK);
    gemm_mma<0><<<gg, 256, SMEM_GEMM>>>(Xh, Xl, Wh + 1*(size_t)Hh*Hh, Wl + 1*(size_t)Hh*Hh,
                                        bk, Kh, Kl, nullptr, 1.0f, NTOK);
    gemm_mma<0><<<gg, 256, SMEM_GEMM>>>(Xh, Xl, Wh + 2*(size_t)Hh*Hh, Wl + 2*(size_t)Hh*Hh,
                                        bv, Vh, Vl, nullptr, 1.0f, NTOK);

    attn_mma<<<dim3((Ss + 63) / 64, Bb * NH_), 128, SMEM_ATT>>>(mask, Ch, Cl);

    gemm_mma<1><<<gg, 256, SMEM_GEMM>>>(Ch, Cl, Wh + 3*(size_t)Hh*Hh, Wl + 3*(size_t)Hh*Hh,
                                        bo, nullptr, nullptr, out, 1.0f, NTOK);
}

// round 17
// speedup vs baseline: 1.0671x; 1.0474x over previous
#include <cuda_runtime.h>
#include <cuda_bf16.h>
#include <math.h>
#include <stdint.h>

#define Bb   32
#define Ss   577
#define Hh   1024
#define NH_  16
#define DH_  64
#define NTOK (Bb*Ss)          // 18464

// ---------------- scratch (__device__ globals; no allocs allowed) ----------
__device__ __align__(16) __nv_bfloat16 g_Xh[(size_t)NTOK*Hh];
__device__ __align__(16) __nv_bfloat16 g_Xl[(size_t)NTOK*Hh];
__device__ __align__(16) __nv_bfloat16 g_Wh[(size_t)4*Hh*Hh];   // [Wq;Wk;Wv;Wo]
__device__ __align__(16) __nv_bfloat16 g_Wl[(size_t)4*Hh*Hh];
// head-major [B,NH,S,DH] bf16 hi/lo
__device__ __align__(16) __nv_bfloat16 g_Qh[(size_t)NTOK*Hh];
__device__ __align__(16) __nv_bfloat16 g_Ql[(size_t)NTOK*Hh];
__device__ __align__(16) __nv_bfloat16 g_Kh[(size_t)NTOK*Hh];
__device__ __align__(16) __nv_bfloat16 g_Kl[(size_t)NTOK*Hh];
__device__ __align__(16) __nv_bfloat16 g_Vh[(size_t)NTOK*Hh];
__device__ __align__(16) __nv_bfloat16 g_Vl[(size_t)NTOK*Hh];
// token-major [B,S,H] bf16 hi/lo (attention output)
__device__ __align__(16) __nv_bfloat16 g_Ch[(size_t)NTOK*Hh];
__device__ __align__(16) __nv_bfloat16 g_Cl[(size_t)NTOK*Hh];

// ---------------- PTX helpers (sm_80-class only; no 'a'-gated features) ----
__device__ __forceinline__ uint32_t smem_u32(const void* p) {
    uint32_t a;
    asm("{ .reg .u64 t; cvta.to.shared.u64 t, %1; cvt.u32.u64 %0, t; }" : "=r"(a) : "l"(p));
    return a;
}
__device__ __forceinline__ void cp16(uint32_t dst, const void* src, int valid) {
    int sz = valid ? 16 : 0;
    asm volatile("cp.async.cg.shared.global [%0], [%1], 16, %2;"
                 :: "r"(dst), "l"(src), "r"(sz) : "memory");
}
#define CP_COMMIT() asm volatile("cp.async.commit_group;" ::: "memory")
#define CP_WAIT0()  asm volatile("cp.async.wait_group 0;" ::: "memory")
#define CP_WAIT1()  asm volatile("cp.async.wait_group 1;" ::: "memory")

#define LDM4(R, ADDR) \
    asm volatile("ldmatrix.sync.aligned.m8n8.x4.shared.b16 {%0,%1,%2,%3}, [%4];" \
        : "=r"((R)[0]), "=r"((R)[1]), "=r"((R)[2]), "=r"((R)[3]) : "r"(ADDR))
#define LDM4T(R, ADDR) \
    asm volatile("ldmatrix.sync.aligned.m8n8.x4.trans.shared.b16 {%0,%1,%2,%3}, [%4];" \
        : "=r"((R)[0]), "=r"((R)[1]), "=r"((R)[2]), "=r"((R)[3]) : "r"(ADDR))

#define MMA16816(D, A, B0, B1) \
    asm volatile("mma.sync.aligned.m16n8k16.row.col.f32.bf16.bf16.f32 " \
        "{%0,%1,%2,%3},{%4,%5,%6,%7},{%8,%9},{%0,%1,%2,%3};" \
        : "+f"((D)[0]), "+f"((D)[1]), "+f"((D)[2]), "+f"((D)[3]) \
        : "r"((A)[0]), "r"((A)[1]), "r"((A)[2]), "r"((A)[3]), "r"(B0), "r"(B1))

__device__ __forceinline__ uint32_t pack_bf16(float lo, float hi) {
    __nv_bfloat162 t = __float22bfloat162_rn(make_float2(lo, hi));
    return *(uint32_t*)&t;
}
__device__ __forceinline__ float bf16_res(float x) {
    return x - __bfloat162float(__float2bfloat16(x));
}

// ---------------- split fp32 -> bf16 hi/lo --------------------------------
__global__ __launch_bounds__(256)
void split_k(const float* __restrict__ x, __nv_bfloat16* __restrict__ hi,
             __nv_bfloat16* __restrict__ lo, int n)
{
    int i = (blockIdx.x * 256 + threadIdx.x) * 4;
    if (i >= n) return;
    float4 v = *(const float4*)(x + i);
    float f[4] = {v.x, v.y, v.z, v.w};
    union { __nv_bfloat16 b[4]; uint2 u; } ph, pl;
#pragma unroll
    for (int k = 0; k < 4; k++) {
        __nv_bfloat16 h = __float2bfloat16(f[k]);
        ph.b[k] = h;
        pl.b[k] = __float2bfloat16(f[k] - __bfloat162float(h));
    }
    *(uint2*)(hi + i) = ph.u;
    *(uint2*)(lo + i) = pl.u;
}

// one launch for all four weight matrices (blockIdx.y selects the matrix)
__global__ __launch_bounds__(256)
void split_w(const float* __restrict__ w0, const float* __restrict__ w1,
             const float* __restrict__ w2, const float* __restrict__ w3,
             __nv_bfloat16* __restrict__ hi, __nv_bfloat16* __restrict__ lo)
{
    const int wsel = blockIdx.y;
    const float* src = (wsel == 0) ? w0 : (wsel == 1) ? w1 : (wsel == 2) ? w2 : w3;
    const size_t base = (size_t)wsel * Hh * Hh;
    int i = (blockIdx.x * 256 + threadIdx.x) * 4;
    float4 v = *(const float4*)(src + i);
    float f[4] = {v.x, v.y, v.z, v.w};
    union { __nv_bfloat16 b[4]; uint2 u; } ph, pl;
#pragma unroll
    for (int k = 0; k < 4; k++) {
        __nv_bfloat16 h = __float2bfloat16(f[k]);
        ph.b[k] = h;
        pl.b[k] = __float2bfloat16(f[k] - __bfloat162float(h));
    }
    *(uint2*)(hi + base + i) = ph.u;
    *(uint2*)(lo + base + i) = pl.u;
}

// ---------------- HMMA split-bf16 GEMM core -------------------------------
// CTA tile 128x128, K-chunk 32, 2-stage cp.async, 256 threads (2M x 4N warps).
// smem rows at 80B pitch (5x16B) -> conflict-free ldmatrix.
#define TILE_B   (128*5*16)           // 10240 B per operand tile
#define SMEM_GEMM (8*TILE_B)          // 2 stages x 4 tiles = 81920 B

// Accumulate C = A @ W^T for one 128x128 tile; acc[4][4][4] per thread.
__device__ __forceinline__ void gemm_core(
    const __nv_bfloat16* __restrict__ Ah, const __nv_bfloat16* __restrict__ Al,
    const __nv_bfloat16* __restrict__ Wh, const __nv_bfloat16* __restrict__ Wl,
    uint32_t sb, int tid, int n0, int wrow, int Nrows,
    int rA, int rW, int hi16, float acc[4][4][4])
{
    auto fill = [&](int chunk, int s) {
        const int k0 = chunk * 32;
        const uint32_t base = sb + s * 4 * TILE_B;
#pragma unroll
        for (int idx = tid; idx < 512; idx += 256) {
            const int r = idx >> 2, c = idx & 3;
            const uint32_t dst = (uint32_t)(r * 5 + c) * 16;
            const int ar = n0 + r;
            const int av = (ar < Nrows);
            const size_t ao = (size_t)(av ? ar : 0) * 1024 + k0 + c * 8;
            cp16(base + dst,              Ah + ao, av);
            cp16(base + TILE_B + dst,     Al + ao, av);
            const size_t wo = (size_t)(wrow + r) * 1024 + k0 + c * 8;
            cp16(base + 2*TILE_B + dst,   Wh + wo, 1);
            cp16(base + 3*TILE_B + dst,   Wl + wo, 1);
        }
    };

    fill(0, 0); CP_COMMIT();

    for (int ch = 0; ch < 32; ch++) {
        if (ch + 1 < 32) { fill(ch + 1, (ch + 1) & 1); CP_COMMIT(); CP_WAIT1(); }
        else             { CP_WAIT0(); }
        __syncthreads();

        const uint32_t base = sb + (ch & 1) * 4 * TILE_B;
#pragma unroll
        for (int ks = 0; ks < 2; ks++) {
            const int c16 = ks * 2 + hi16;
            uint32_t bh[2][4], bl[2][4];
#pragma unroll
            for (int nb = 0; nb < 2; nb++) {
                const uint32_t off = (uint32_t)((rW + nb*16) * 5 + c16) * 16;
                LDM4(bh[nb], base + 2*TILE_B + off);
                LDM4(bl[nb], base + 3*TILE_B + off);
            }
#pragma unroll
            for (int ma = 0; ma < 4; ma++) {
                uint32_t ah[4], al[4];
                const uint32_t off = (uint32_t)((rA + ma*16) * 5 + c16) * 16;
                LDM4(ah, base + off);
                LDM4(al, base + TILE_B + off);
#pragma unroll
                for (int n8 = 0; n8 < 4; n8++) {
                    const int nb = n8 >> 1, h = n8 & 1;
                    MMA16816(acc[ma][n8], ah, bh[nb][0+h], bh[nb][2+h]);
                    MMA16816(acc[ma][n8], ah, bl[nb][0+h], bl[nb][2+h]);
                    MMA16816(acc[ma][n8], al, bh[nb][0+h], bh[nb][2+h]);
                }
            }
        }
        __syncthreads();
    }
}

// Fused QKV projection: blockIdx.y in [0,24) covers concatenated [Wq;Wk;Wv].
__global__ __launch_bounds__(256, 2)
void gemm_qkv(const __nv_bfloat16* __restrict__ Ah, const __nv_bfloat16* __restrict__ Al,
              const __nv_bfloat16* __restrict__ Wh, const __nv_bfloat16* __restrict__ Wl,
              const float* __restrict__ bq, const float* __restrict__ bk,
              const float* __restrict__ bv,
              __nv_bfloat16* __restrict__ Qh, __nv_bfloat16* __restrict__ Ql,
              __nv_bfloat16* __restrict__ Kh, __nv_bfloat16* __restrict__ Kl,
              __nv_bfloat16* __restrict__ Vh, __nv_bfloat16* __restrict__ Vl,
              int Nrows)
{
    extern __shared__ __align__(128) char smem[];
    const uint32_t sb = smem_u32(smem);
    const int tid  = threadIdx.x;
    const int wid  = tid >> 5;
    const int lane = tid & 31;
    const int n0 = blockIdx.x * 128;
    const int m0 = blockIdx.y * 128;           // 0..3071 over [Wq;Wk;Wv]
    const int which = m0 >> 10;                // 0=Q,1=K,2=V
    const int warp_m = wid & 1;
    const int warp_n = wid >> 1;

    const float* bias = (which == 0) ? bq : (which == 1) ? bk : bv;
    __nv_bfloat16* outh = (which == 0) ? Qh : (which == 1) ? Kh : Vh;
    __nv_bfloat16* outl = (which == 0) ? Ql : (which == 1) ? Kl : Vl;
    const float scale = (which == 0) ? 0.125f : 1.0f;

    float acc[4][4][4];
#pragma unroll
    for (int i = 0; i < 4; i++)
#pragma unroll
        for (int j = 0; j < 4; j++)
#pragma unroll
            for (int d = 0; d < 4; d++) acc[i][j][d] = 0.f;

    const int rA = warp_m * 64 + (lane & 15);
    const int rW = warp_n * 32 + (lane & 15);
    const int hi16 = lane >> 4;

    gemm_core(Ah, Al, Wh, Wl, sb, tid, n0, m0, Nrows, rA, rW, hi16, acc);

    float bias2[4][2];
#pragma unroll
    for (int n8 = 0; n8 < 4; n8++) {
        const int m = (m0 & 1023) + warp_n*32 + n8*8 + (lane & 3)*2;
        bias2[n8][0] = bias[m];
        bias2[n8][1] = bias[m + 1];
    }
#pragma unroll
    for (int ma = 0; ma < 4; ma++)
#pragma unroll
        for (int half = 0; half < 2; half++) {
            const int n = n0 + warp_m*64 + ma*16 + (lane >> 2) + half*8;
            if (n >= Nrows) continue;
            const int b = n / Ss, s = n - b * Ss;
#pragma unroll
            for (int n8 = 0; n8 < 4; n8++) {
                const int m = (m0 & 1023) + warp_n*32 + n8*8 + (lane & 3)*2;
                const float vx = (acc[ma][n8][2*half + 0] + bias2[n8][0]) * scale;
                const float vy = (acc[ma][n8][2*half + 1] + bias2[n8][1]) * scale;
                const int h = m >> 6, d = m & 63;
                const size_t off = (((size_t)(b*NH_ + h))*Ss + s)*DH_ + d;
                *(uint32_t*)(outh + off) = pack_bf16(vx, vy);
                *(uint32_t*)(outl + off) = pack_bf16(bf16_res(vx), bf16_res(vy));
            }
        }
}

// O projection: fp32 token-major output.
__global__ __launch_bounds__(256, 2)
void gemm_o(const __nv_bfloat16* __restrict__ Ah, const __nv_bfloat16* __restrict__ Al,
            const __nv_bfloat16* __restrict__ Wh, const __nv_bfloat16* __restrict__ Wl,
            const float* __restrict__ bias, float* __restrict__ outf, int Nrows)
{
    extern __shared__ __align__(128) char smem[];
    const uint32_t sb = smem_u32(smem);
    const int tid  = threadIdx.x;
    const int wid  = tid >> 5;
    const int lane = tid & 31;
    const int n0 = blockIdx.x * 128;
    const int m0 = blockIdx.y * 128;
    const int warp_m = wid & 1;
    const int warp_n = wid >> 1;

    float acc[4][4][4];
#pragma unroll
    for (int i = 0; i < 4; i++)
#pragma unroll
        for (int j = 0; j < 4; j++)
#pragma unroll
            for (int d = 0; d < 4; d++) acc[i][j][d] = 0.f;

    const int rA = warp_m * 64 + (lane & 15);
    const int rW = warp_n * 32 + (lane & 15);
    const int hi16 = lane >> 4;

    gemm_core(Ah, Al, Wh, Wl, sb, tid, n0, m0, Nrows, rA, rW, hi16, acc);

    float bias2[4][2];
#pragma unroll
    for (int n8 = 0; n8 < 4; n8++) {
        const int m = m0 + warp_n*32 + n8*8 + (lane & 3)*2;
        bias2[n8][0] = bias[m];
        bias2[n8][1] = bias[m + 1];
    }
#pragma unroll
    for (int ma = 0; ma < 4; ma++)
#pragma unroll
        for (int half = 0; half < 2; half++) {
            const int n = n0 + warp_m*64 + ma*16 + (lane >> 2) + half*8;
            if (n >= Nrows) continue;
#pragma unroll
            for (int n8 = 0; n8 < 4; n8++) {
                const int m = m0 + warp_n*32 + n8*8 + (lane & 3)*2;
                float2 v;
                v.x = acc[ma][n8][2*half + 0] + bias2[n8][0];
                v.y = acc[ma][n8][2*half + 1] + bias2[n8][1];
                *(float2*)(outf + (size_t)n*1024 + m) = v;
            }
        }
}

// ---------------------------------------------------------------------------
// HMMA flash attention. Grid (10, 512), 128 threads (4 warps x 16 q rows).
// Split-bf16 3-pass for QK^T and PV. Multiplicative mask (ref semantics).
// SINGLE-stage KV (smem 57.9KB) -> 3 CTAs/SM; cross-CTA overlap hides the
// exposed per-tile load latency.
// Smem rows at 144B pitch ((r*9+c)%8 permutes -> conflict-free ldmatrix).
// ---------------------------------------------------------------------------
#define AP       9                    // 16B units per row
#define ATILE_B  (64*AP*16)           // 9216 B per 64x64 bf16 tile
#define SM_Q     2560                 // Qh, Ql
#define SM_KV    (SM_Q + 2*ATILE_B)   // single stage {Kh,Kl,Vh,Vl}
#define SMEM_ATT (SM_KV + 4*ATILE_B)  // 57856 B

__global__ __launch_bounds__(128, 3)
void attn_mma(const float* __restrict__ mask,
              __nv_bfloat16* __restrict__ Ch, __nv_bfloat16* __restrict__ Cl)
{
    extern __shared__ __align__(128) char smem[];
    const uint32_t sb = smem_u32(smem);
    float* mask_s = (float*)smem;

    const int bh = blockIdx.y;
    const int b = bh >> 4, h = bh & 15;
    const int q0 = blockIdx.x * 64;
    const int tid = threadIdx.x;
    const int wid = tid >> 5;
    const int lane = tid & 31;

    const __nv_bfloat16* Qhg = g_Qh + (size_t)bh * Ss * DH_;
    const __nv_bfloat16* Qlg = g_Ql + (size_t)bh * Ss * DH_;
    const __nv_bfloat16* Khg = g_Kh + (size_t)bh * Ss * DH_;
    const __nv_bfloat16* Klg = g_Kl + (size_t)bh * Ss * DH_;
    const __nv_bfloat16* Vhg = g_Vh + (size_t)bh * Ss * DH_;
    const __nv_bfloat16* Vlg = g_Vl + (size_t)bh * Ss * DH_;

    // mask row -> smem (zero-padded to 640)
    for (int i = tid; i < 640; i += 128)
        mask_s[i] = (i < Ss) ? mask[b * Ss + i] : 0.f;

    // Q tiles (once); committed with the first KV fill's group
    for (int idx = tid; idx < 512; idx += 128) {
        const int r = idx >> 3, c = idx & 7;
        const uint32_t dst = (uint32_t)(r * AP + c) * 16;
        const int q = q0 + r;
        const int v = (q < Ss);
        const size_t off = (size_t)(v ? q : 0) * 64 + c * 8;
        cp16(sb + SM_Q + dst,           Qhg + off, v);
        cp16(sb + SM_Q + ATILE_B + dst, Qlg + off, v);
    }

    auto fillKV = [&](int kt) {
        const int k0 = kt * 64;
        const uint32_t base = sb + SM_KV;
        for (int idx = tid; idx < 512; idx += 128) {
            const int r = idx >> 3, c = idx & 7;
            const uint32_t dst = (uint32_t)(r * AP + c) * 16;
            const int k = k0 + r;
            const int v = (k < Ss);
            const size_t off = (size_t)(v ? k : 0) * 64 + c * 8;
            cp16(base + dst,             Khg + off, v);
            cp16(base + ATILE_B + dst,   Klg + off, v);
            cp16(base + 2*ATILE_B + dst, Vhg + off, v);
            cp16(base + 3*ATILE_B + dst, Vlg + off, v);
        }
    };

    float m0v = -1e30f, m1v = -1e30f, l0 = 0.f, l1 = 0.f;
    float ctx[8][4];
#pragma unroll
    for (int i = 0; i < 8; i++)
#pragma unroll
        for (int j = 0; j < 4; j++) ctx[i][j] = 0.f;

    const int rQ = wid * 16 + (lane & 15);
    const int hi16 = lane >> 4;

    for (int kt = 0; kt < 10; kt++) {
        __syncthreads();   // all warps done reading previous KV tile
        fillKV(kt);
        CP_COMMIT(); CP_WAIT0();
        __syncthreads();   // KV (and, on kt=0, Q) visible to all

        const uint32_t base = sb + SM_KV;
        const uint32_t kHb = base, kLb = base + ATILE_B;
        const uint32_t vHb = base + 2*ATILE_B, vLb = base + 3*ATILE_B;

        // ---- scores = Q . K^T (3-pass split) ----
        float s[8][4];
#pragma unroll
        for (int i = 0; i < 8; i++)
#pragma unroll
            for (int j = 0; j < 4; j++) s[i][j] = 0.f;

#pragma unroll
        for (int kk = 0; kk < 4; kk++) {
            const int c16 = kk * 2 + hi16;
            uint32_t qh[4], ql[4];
            const uint32_t qoff = (uint32_t)(rQ * AP + c16) * 16;
            LDM4(qh, sb + SM_Q + qoff);
            LDM4(ql, sb + SM_Q + ATILE_B + qoff);
#pragma unroll
            for (int nb = 0; nb < 4; nb++) {
                uint32_t kh[4], kl[4];
                const uint32_t koff = (uint32_t)((nb*16 + (lane & 15)) * AP + c16) * 16;
                LDM4(kh, kHb + koff);
                LDM4(kl, kLb + koff);
#pragma unroll
                for (int hh = 0; hh < 2; hh++) {
                    MMA16816(s[2*nb+hh], qh, kh[0+hh], kh[2+hh]);
                    MMA16816(s[2*nb+hh], qh, kl[0+hh], kl[2+hh]);
                    MMA16816(s[2*nb+hh], ql, kh[0+hh], kh[2+hh]);
                }
            }
        }

        // ---- multiplicative mask + key padding ----
        const int k0 = kt * 64;
#pragma unroll
        for (int n8 = 0; n8 < 8; n8++) {
            const int kb = k0 + n8*8 + 2*(lane & 3);
            const float mA = mask_s[kb], mB = mask_s[kb + 1];
            const bool okA = (kb < Ss), okB = (kb + 1 < Ss);
            s[n8][0] = okA ? s[n8][0]*mA : -1e30f;
            s[n8][1] = okB ? s[n8][1]*mB : -1e30f;
            s[n8][2] = okA ? s[n8][2]*mA : -1e30f;
            s[n8][3] = okB ? s[n8][3]*mB : -1e30f;
        }

        // ---- online softmax (rows r0=lane>>2, r1=r0+8; reduce over lane&3) ----
        float tm0 = -1e30f, tm1 = -1e30f;
#pragma unroll
        for (int n8 = 0; n8 < 8; n8++) {
            tm0 = fmaxf(tm0, fmaxf(s[n8][0], s[n8][1]));
            tm1 = fmaxf(tm1, fmaxf(s[n8][2], s[n8][3]));
        }
#pragma unroll
        for (int o = 1; o <= 2; o <<= 1) {
            tm0 = fmaxf(tm0, __shfl_xor_sync(0xffffffffu, tm0, o));
            tm1 = fmaxf(tm1, __shfl_xor_sync(0xffffffffu, tm1, o));
        }
        const float mn0 = fmaxf(m0v, tm0), mn1 = fmaxf(m1v, tm1);
        const float c0 = __expf(m0v - mn0), c1 = __expf(m1v - mn1);
        float rs0 = 0.f, rs1 = 0.f;
#pragma unroll
        for (int n8 = 0; n8 < 8; n8++) {
            s[n8][0] = __expf(s[n8][0] - mn0); rs0 += s[n8][0];
            s[n8][1] = __expf(s[n8][1] - mn0); rs0 += s[n8][1];
            s[n8][2] = __expf(s[n8][2] - mn1); rs1 += s[n8][2];
            s[n8][3] = __expf(s[n8][3] - mn1); rs1 += s[n8][3];
        }
#pragma unroll
        for (int o = 1; o <= 2; o <<= 1) {
            rs0 += __shfl_xor_sync(0xffffffffu, rs0, o);
            rs1 += __shfl_xor_sync(0xffffffffu, rs1, o);
        }
        l0 = l0*c0 + rs0; l1 = l1*c1 + rs1;
        m0v = mn0; m1v = mn1;
#pragma unroll
        for (int n8 = 0; n8 < 8; n8++) {
            ctx[n8][0] *= c0; ctx[n8][1] *= c0;
            ctx[n8][2] *= c1; ctx[n8][3] *= c1;
        }

        // ---- ctx += P @ V (3-pass split; P frags reused from s regs) ----
#pragma unroll
        for (int t = 0; t < 4; t++) {
            uint32_t ph[4], pl[4];
            ph[0] = pack_bf16(s[2*t][0],   s[2*t][1]);
            ph[1] = pack_bf16(s[2*t][2],   s[2*t][3]);
            ph[2] = pack_bf16(s[2*t+1][0], s[2*t+1][1]);
            ph[3] = pack_bf16(s[2*t+1][2], s[2*t+1][3]);
            pl[0] = pack_bf16(bf16_res(s[2*t][0]),   bf16_res(s[2*t][1]));
            pl[1] = pack_bf16(bf16_res(s[2*t][2]),   bf16_res(s[2*t][3]));
            pl[2] = pack_bf16(bf16_res(s[2*t+1][0]), bf16_res(s[2*t+1][1]));
            pl[3] = pack_bf16(bf16_res(s[2*t+1][2]), bf16_res(s[2*t+1][3]));
#pragma unroll
            for (int g = 0; g < 4; g++) {
                uint32_t vh[4], vl[4];
                const uint32_t voff = (uint32_t)((t*16 + (lane & 15)) * AP + g*2 + hi16) * 16;
                LDM4T(vh, vHb + voff);
                LDM4T(vl, vLb + voff);
#pragma unroll
                for (int hh = 0; hh < 2; hh++) {
                    MMA16816(ctx[2*g+hh], ph, vh[2*hh], vh[2*hh+1]);
                    MMA16816(ctx[2*g+hh], ph, vl[2*hh], vl[2*hh+1]);
                    MMA16816(ctx[2*g+hh], pl, vh[2*hh], vh[2*hh+1]);
                }
            }
        }
    }

    // ---- epilogue: bf16 hi/lo token-major [B,S,H] ----
    const float i0 = 1.f / l0, i1 = 1.f / l1;
    const int qr = q0 + wid*16 + (lane >> 2);
    const int d0 = 2*(lane & 3);
#pragma unroll
    for (int n8 = 0; n8 < 8; n8++) {
        const int d = h*64 + n8*8 + d0;
        if (qr < Ss) {
            const float vx = ctx[n8][0]*i0, vy = ctx[n8][1]*i0;
            const size_t off = ((size_t)(b*Ss + qr))*Hh + d;
            *(uint32_t*)(Ch + off) = pack_bf16(vx, vy);
            *(uint32_t*)(Cl + off) = pack_bf16(bf16_res(vx), bf16_res(vy));
        }
        if (qr + 8 < Ss) {
            const float vx = ctx[n8][2]*i1, vy = ctx[n8][3]*i1;
            const size_t off = ((size_t)(b*Ss + qr + 8))*Hh + d;
            *(uint32_t*)(Ch + off) = pack_bf16(vx, vy);
            *(uint32_t*)(Cl + off) = pack_bf16(bf16_res(vx), bf16_res(vy));
        }
    }
}

// ---------------------------------------------------------------------------
extern "C" void kernel_launch(void* const* d_in, const int* in_sizes, int n_in,
                              void* d_out, int out_size)
{
    const float* X    = (const float*)d_in[0];
    const float* mask = (const float*)d_in[1];
    const float* Wq   = (const float*)d_in[2];
    const float* bq   = (const float*)d_in[3];
    const float* Wk   = (const float*)d_in[4];
    const float* bk   = (const float*)d_in[5];
    const float* Wv   = (const float*)d_in[6];
    const float* bv   = (const float*)d_in[7];
    const float* Wo   = (const float*)d_in[8];
    const float* bo   = (const float*)d_in[9];
    float* out = (float*)d_out;

    __nv_bfloat16 *Xh, *Xl, *Wh, *Wl, *Qh, *Ql, *Kh, *Kl, *Vh, *Vl, *Ch, *Cl;
    cudaGetSymbolAddress((void**)&Xh, g_Xh);
    cudaGetSymbolAddress((void**)&Xl, g_Xl);
    cudaGetSymbolAddress((void**)&Wh, g_Wh);
    cudaGetSymbolAddress((void**)&Wl, g_Wl);
    cudaGetSymbolAddress((void**)&Qh, g_Qh);
    cudaGetSymbolAddress((void**)&Ql, g_Ql);
    cudaGetSymbolAddress((void**)&Kh, g_Kh);
    cudaGetSymbolAddress((void**)&Kl, g_Kl);
    cudaGetSymbolAddress((void**)&Vh, g_Vh);
    cudaGetSymbolAddress((void**)&Vl, g_Vl);
    cudaGetSymbolAddress((void**)&Ch, g_Ch);
    cudaGetSymbolAddress((void**)&Cl, g_Cl);

    static bool attr_done = false;
    if (!attr_done) {
        cudaFuncSetAttribute(gemm_qkv, cudaFuncAttributeMaxDynamicSharedMemorySize, SMEM_GEMM);
        cudaFuncSetAttribute(gemm_o,   cudaFuncAttributeMaxDynamicSharedMemorySize, SMEM_GEMM);
        cudaFuncSetAttribute(attn_mma, cudaFuncAttributeMaxDynamicSharedMemorySize, SMEM_ATT);
        attr_done = true;
    }

    // split inputs to bf16 hi/lo
    split_k<<<NTOK, 256>>>(X, Xh, Xl, NTOK * Hh);
    split_w<<<dim3(1024, 4), 256>>>(Wq, Wk, Wv, Wo, Wh, Wl);

    // fused QKV projection (one launch; Q pre-scaled by 1/sqrt(DH)=0.125)
    gemm_qkv<<<dim3((NTOK + 127) / 128, 3 * Hh / 128), 256, SMEM_GEMM>>>(
        Xh, Xl, Wh, Wl, bq, bk, bv, Qh, Ql, Kh, Kl, Vh, Vl, NTOK);

    attn_mma<<<dim3((Ss + 63) / 64, Bb * NH_), 128, SMEM_ATT>>>(mask, Ch, Cl);

    gemm_o<<<dim3((NTOK + 127) / 128, Hh / 128), 256, SMEM_GEMM>>>(
        Ch, Cl, Wh + 3*(size_t)Hh*Hh, Wl + 3*(size_t)Hh*Hh, bo, out, NTOK);
}